// round 14
// baseline (speedup 1.0000x reference)
#include <cuda_runtime.h>
#include <cstddef>

// 7x7 VALID conv, 4096x4096 fp32 -> 4090x4090 fp32, + bias.
// R14 = R13 (direct imm-offset LDG, no smem/barriers, P/Q weight-pair FFMA2,
// weights in __constant__, 4 rows x 8 cols/thread) + warp-shuffle halo:
// E[4..6] come from the tx-neighbor's E[0..2] via shfl.down (width 16);
// only tx==15 lanes self-load the halo. LDG instr/row: 3.5 -> ~2.1.

#define IN_W 4096
#define IN_H 4096
#define OUT_W 4090
#define OUT_H 4090

#define TILE_W 128
#define TILE_H 32

typedef unsigned long long u64;

__constant__ u64 c_wp[60];   // [kr*8+0..3]=P, [kr*8+4..7]=Q, [56]=(bias,bias)
__device__ u64 g_pack[60];

__device__ __forceinline__ u64 pk(float a, float b) {
    u64 r;
    asm("mov.b64 %0, {%1, %2};" : "=l"(r) : "f"(a), "f"(b));
    return r;
}
__device__ __forceinline__ void upk(u64 v, float &a, float &b) {
    asm("mov.b64 {%0, %1}, %2;" : "=f"(a), "=f"(b) : "l"(v));
}
__device__ __forceinline__ void fma2(u64 &d, u64 a, u64 b) {
    asm("fma.rn.f32x2 %0, %1, %2, %3;" : "=l"(d) : "l"(a), "l"(b), "l"(d));
}
__device__ __forceinline__ u64 shfld1(u64 v) {
    // shift by one lane within 16-lane groups; lane 15 of group keeps own value
    return __shfl_down_sync(0xffffffffu, v, 1, 16);
}

__global__ void prep_kernel(const float* __restrict__ w,
                            const float* __restrict__ bias)
{
    const int t = threadIdx.x;
    if (t < 7) {
        const float* wr = w + t * 7;
        float w0 = wr[0], w1 = wr[1], w2 = wr[2], w3 = wr[3],
              w4 = wr[4], w5 = wr[5], w6 = wr[6];
        g_pack[t * 8 + 0] = pk(w0, w1);
        g_pack[t * 8 + 1] = pk(w2, w3);
        g_pack[t * 8 + 2] = pk(w4, w5);
        g_pack[t * 8 + 3] = pk(w6, 0.f);
        g_pack[t * 8 + 4] = pk(0.f, w0);
        g_pack[t * 8 + 5] = pk(w1, w2);
        g_pack[t * 8 + 6] = pk(w3, w4);
        g_pack[t * 8 + 7] = pk(w5, w6);
    } else if (t == 7) {
        float b = bias[0];
        g_pack[56] = pk(b, b);
    } else if (t < 11) {
        g_pack[t + 50] = 0ull;   // pad 57..59
    }
}

__global__ __launch_bounds__(128)
void conv7x7_kernel(const float* __restrict__ x,
                    float* __restrict__ out)
{
    const int tx = threadIdx.x;     // 0..15
    const int ty = threadIdx.y;     // 0..7

    const int bx = blockIdx.x * TILE_W;
    const int by = blockIdx.y * TILE_H;

    const int gx = bx + tx * 8;     // input col base for this thread
    const int ry = by + ty * 4;     // first output row

    const bool is_edge = (tx == 15);           // halo self-load lane
    const bool c2ok = (gx + 12 <= IN_W);       // halo chunk2 in-bounds
    const bool c3ok = (gx + 14 <= IN_W);       // halo chunk3 in-bounds

    // acc[ar][j]: packed partials of output j of row ry+ar (out = lo + hi)
    u64 acc[4][8];
    #pragma unroll
    for (int a = 0; a < 4; a++)
        #pragma unroll
        for (int j = 0; j < 8; j++) acc[a][j] = 0ull;

    const bool rows_fast = (ry + 9 <= IN_H - 1);
    const char* bp8 = reinterpret_cast<const char*>(x + (size_t)ry * IN_W + gx);

    #pragma unroll
    for (int r = 0; r < 10; r++) {
        // E[m] = (in[row][gx+2m], in[row][gx+2m+1]), m=0..6
        u64 E[7];
        const char* rp;
        if (rows_fast) {
            rp = bp8 + r * (IN_W * 4);          // immediate offsets in LDG
        } else {
            int gy = ry + r; if (gy > IN_H - 1) gy = IN_H - 1;
            rp = reinterpret_cast<const char*>(x + (size_t)gy * IN_W + gx);
        }
        // Own 32B: 2x LDG.128
        {
            ulonglong2 q0 = *reinterpret_cast<const ulonglong2*>(rp);
            ulonglong2 q1 = *reinterpret_cast<const ulonglong2*>(rp + 16);
            E[0] = q0.x; E[1] = q0.y;
            E[2] = q1.x; E[3] = q1.y;
        }
        // Halo self-load for tx==15 only (predicated)
        u64 H4 = 0ull, H5 = 0ull, H6 = 0ull;
        if (is_edge) {
            if (c2ok) {
                ulonglong2 q2 = *reinterpret_cast<const ulonglong2*>(rp + 32);
                H4 = q2.x; H5 = q2.y;
            }
            if (c3ok) {
                H6 = *reinterpret_cast<const u64*>(rp + 48);
            }
        }
        // Halo via shuffle from tx+1 (same 16-lane group = same ty)
        E[4] = shfld1(E[0]);
        E[5] = shfld1(E[1]);
        E[6] = shfld1(E[2]);
        if (is_edge) { E[4] = H4; E[5] = H5; E[6] = H6; }

        #pragma unroll
        for (int ar = 0; ar < 4; ar++) {
            const int kr = r - ar;
            if (kr >= 0 && kr <= 6) {
                #pragma unroll
                for (int t = 0; t < 4; t++) {
                    const u64 Pt = c_wp[kr * 8 + t];
                    const u64 Qt = c_wp[kr * 8 + 4 + t];
                    #pragma unroll
                    for (int v = 0; v < 4; v++) {
                        fma2(acc[ar][2 * v],     E[v + t], Pt);
                        fma2(acc[ar][2 * v + 1], E[v + t], Qt);
                    }
                }
            }
        }
    }

    // ---- Epilogue: out[j] = acc.lo + acc.hi + bias; float2 stores ----
    float bv, bdummy;
    upk(c_wp[56], bv, bdummy);
    #pragma unroll
    for (int ar = 0; ar < 4; ar++) {
        const int oy = ry + ar;
        if (oy < OUT_H) {
            float* orow = out + (size_t)oy * OUT_W;
            #pragma unroll
            for (int v = 0; v < 4; v++) {
                const int ox = gx + 2 * v;
                if (ox < OUT_W) {
                    float l0, h0, l1, h1;
                    upk(acc[ar][2 * v],     l0, h0);
                    upk(acc[ar][2 * v + 1], l1, h1);
                    float2 o;
                    o.x = l0 + h0 + bv;
                    o.y = l1 + h1 + bv;
                    *reinterpret_cast<float2*>(orow + ox) = o;
                }
            }
        }
    }
}

extern "C" void kernel_launch(void* const* d_in, const int* in_sizes, int n_in,
                              void* d_out, int out_size)
{
    const float* x    = (const float*)d_in[0];
    const float* w    = (const float*)d_in[1];
    const float* bias = (const float*)d_in[2];
    float* out = (float*)d_out;

    prep_kernel<<<1, 32>>>(w, bias);

    void* dst = nullptr;
    void* src = nullptr;
    cudaGetSymbolAddress(&dst, c_wp);
    cudaGetSymbolAddress(&src, g_pack);
    cudaMemcpyAsync(dst, src, 60 * sizeof(u64), cudaMemcpyDeviceToDevice);

    dim3 block(16, 8);
    dim3 grid((OUT_W + TILE_W - 1) / TILE_W,   // 32
              (OUT_H + TILE_H - 1) / TILE_H);  // 128
    conv7x7_kernel<<<grid, block>>>(x, out);
}

// round 15
// speedup vs baseline: 1.0466x; 1.0466x over previous
#include <cuda_runtime.h>
#include <cstddef>

// 7x7 VALID conv, 4096x4096 fp32 -> 4090x4090 fp32, + bias.
// R15 = R13 structure (direct imm-offset LDG, no smem/barriers, P/Q weight-pair
// FFMA2, weights in __constant__) with 3 output rows x 8 cols per thread:
// 48 acc regs instead of 64 -> ~80 total regs -> 6 blocks/SM (24 warps, +20%
// latency hiding) at +20% L1 load instructions. Probes the R12<->R13 occupancy
// /halo tradeoff at its midpoint.
// Block 16x8 = 128 thr; tile 128(w) x 24(h); thread: 3 rows x 8 cols.

#define IN_W 4096
#define IN_H 4096
#define OUT_W 4090
#define OUT_H 4090

#define TILE_W 128
#define TILE_H 24

typedef unsigned long long u64;

__constant__ u64 c_wp[60];   // [kr*8+0..3]=P, [kr*8+4..7]=Q, [56]=(bias,bias)
__device__ u64 g_pack[60];

__device__ __forceinline__ u64 pk(float a, float b) {
    u64 r;
    asm("mov.b64 %0, {%1, %2};" : "=l"(r) : "f"(a), "f"(b));
    return r;
}
__device__ __forceinline__ void upk(u64 v, float &a, float &b) {
    asm("mov.b64 {%0, %1}, %2;" : "=f"(a), "=f"(b) : "l"(v));
}
__device__ __forceinline__ void fma2(u64 &d, u64 a, u64 b) {
    asm("fma.rn.f32x2 %0, %1, %2, %3;" : "=l"(d) : "l"(a), "l"(b), "l"(d));
}

__global__ void prep_kernel(const float* __restrict__ w,
                            const float* __restrict__ bias)
{
    const int t = threadIdx.x;
    if (t < 7) {
        const float* wr = w + t * 7;
        float w0 = wr[0], w1 = wr[1], w2 = wr[2], w3 = wr[3],
              w4 = wr[4], w5 = wr[5], w6 = wr[6];
        g_pack[t * 8 + 0] = pk(w0, w1);
        g_pack[t * 8 + 1] = pk(w2, w3);
        g_pack[t * 8 + 2] = pk(w4, w5);
        g_pack[t * 8 + 3] = pk(w6, 0.f);
        g_pack[t * 8 + 4] = pk(0.f, w0);
        g_pack[t * 8 + 5] = pk(w1, w2);
        g_pack[t * 8 + 6] = pk(w3, w4);
        g_pack[t * 8 + 7] = pk(w5, w6);
    } else if (t == 7) {
        float b = bias[0];
        g_pack[56] = pk(b, b);
    } else if (t < 11) {
        g_pack[t + 50] = 0ull;   // pad 57..59
    }
}

__global__ __launch_bounds__(128)
void conv7x7_kernel(const float* __restrict__ x,
                    float* __restrict__ out)
{
    const int tx = threadIdx.x;     // 0..15
    const int ty = threadIdx.y;     // 0..7

    const int bx = blockIdx.x * TILE_W;
    const int by = blockIdx.y * TILE_H;

    const int gx = bx + tx * 8;     // input col base for this thread
    const int ry = by + ty * 3;     // first output row

    // Column-edge flags (only tx=15 of the last bx fails)
    const bool c2ok = (gx + 12 <= IN_W);   // chunk2: cols gx+8..gx+11
    const bool c3ok = (gx + 14 <= IN_W);   // chunk3: cols gx+12..gx+13

    // acc[ar][j]: packed partials of output j of row ry+ar (out = lo + hi)
    u64 acc[3][8];
    #pragma unroll
    for (int a = 0; a < 3; a++)
        #pragma unroll
        for (int j = 0; j < 8; j++) acc[a][j] = 0ull;

    const bool rows_fast = (ry + 8 <= IN_H - 1);
    const char* bp8 = reinterpret_cast<const char*>(x + (size_t)ry * IN_W + gx);

    #pragma unroll
    for (int r = 0; r < 9; r++) {
        // E[m] = (in[row][gx+2m], in[row][gx+2m+1]), m=0..6
        u64 E[7];
        const char* rp;
        if (rows_fast) {
            rp = bp8 + r * (IN_W * 4);          // immediate offsets in LDG
        } else {
            int gy = ry + r; if (gy > IN_H - 1) gy = IN_H - 1;
            rp = reinterpret_cast<const char*>(x + (size_t)gy * IN_W + gx);
        }
        {
            ulonglong2 q0 = *reinterpret_cast<const ulonglong2*>(rp);
            ulonglong2 q1 = *reinterpret_cast<const ulonglong2*>(rp + 16);
            E[0] = q0.x; E[1] = q0.y;
            E[2] = q1.x; E[3] = q1.y;
            if (c2ok) {
                ulonglong2 q2 = *reinterpret_cast<const ulonglong2*>(rp + 32);
                E[4] = q2.x; E[5] = q2.y;
            } else { E[4] = 0ull; E[5] = 0ull; }
            if (c3ok) {
                E[6] = *reinterpret_cast<const u64*>(rp + 48);
            } else { E[6] = 0ull; }
        }

        #pragma unroll
        for (int ar = 0; ar < 3; ar++) {
            const int kr = r - ar;
            if (kr >= 0 && kr <= 6) {
                #pragma unroll
                for (int t = 0; t < 4; t++) {
                    const u64 Pt = c_wp[kr * 8 + t];
                    const u64 Qt = c_wp[kr * 8 + 4 + t];
                    #pragma unroll
                    for (int v = 0; v < 4; v++) {
                        fma2(acc[ar][2 * v],     E[v + t], Pt);
                        fma2(acc[ar][2 * v + 1], E[v + t], Qt);
                    }
                }
            }
        }
    }

    // ---- Epilogue: out[j] = acc.lo + acc.hi + bias; float2 stores ----
    float bv, bdummy;
    upk(c_wp[56], bv, bdummy);
    #pragma unroll
    for (int ar = 0; ar < 3; ar++) {
        const int oy = ry + ar;
        if (oy < OUT_H) {
            float* orow = out + (size_t)oy * OUT_W;
            #pragma unroll
            for (int v = 0; v < 4; v++) {
                const int ox = gx + 2 * v;
                if (ox < OUT_W) {
                    float l0, h0, l1, h1;
                    upk(acc[ar][2 * v],     l0, h0);
                    upk(acc[ar][2 * v + 1], l1, h1);
                    float2 o;
                    o.x = l0 + h0 + bv;
                    o.y = l1 + h1 + bv;
                    *reinterpret_cast<float2*>(orow + ox) = o;
                }
            }
        }
    }
}

extern "C" void kernel_launch(void* const* d_in, const int* in_sizes, int n_in,
                              void* d_out, int out_size)
{
    const float* x    = (const float*)d_in[0];
    const float* w    = (const float*)d_in[1];
    const float* bias = (const float*)d_in[2];
    float* out = (float*)d_out;

    prep_kernel<<<1, 32>>>(w, bias);

    void* dst = nullptr;
    void* src = nullptr;
    cudaGetSymbolAddress(&dst, c_wp);
    cudaGetSymbolAddress(&src, g_pack);
    cudaMemcpyAsync(dst, src, 60 * sizeof(u64), cudaMemcpyDeviceToDevice);

    dim3 block(16, 8);
    dim3 grid((OUT_W + TILE_W - 1) / TILE_W,   // 32
              (OUT_H + TILE_H - 1) / TILE_H);  // 171
    conv7x7_kernel<<<grid, block>>>(x, out);
}